// round 4
// baseline (speedup 1.0000x reference)
#include <cuda_runtime.h>

// CommNet forward: B=8192, N=64, D=128, O=16
//   H1 = tanh(wH1 * obs)
//   C1 = (sum_n H1 - H1) / (N-1)
//   H2 = tanh(wH2*H1 + wC2*C1) + obs
//   out = H2 @ w_out + b_out
//
// One CTA per batch element. 128 threads = one per feature d.
// Single smem tile holds obs, then is overwritten in-place with H2.

#define N_AG 64
#define DIM  128
#define OUTD 16
#define PITCH 132   // floats; 132*4=528 B rows: 16B aligned, mild GEMV conflicts only

__device__ __forceinline__ float tanh_fast(float x) {
    float y;
    asm("tanh.approx.f32 %0, %1;" : "=f"(y) : "f"(x));
    return y;
}

__global__ __launch_bounds__(128, 4)
void commnet_kernel(const float* __restrict__ obs,
                    const float* __restrict__ wH1,
                    const float* __restrict__ wH2,
                    const float* __restrict__ wC2,
                    const float* __restrict__ wout,
                    const float* __restrict__ bout,
                    float* __restrict__ out)
{
    __shared__ float s[N_AG * PITCH];       // 33,792 B: obs tile -> H2 tile (in place)
    __shared__ float ws[DIM * OUTD];        // 8,192 B: w_out [d][o]
    __shared__ float bs[OUTD];

    const int tid = threadIdx.x;            // 0..127
    const int b   = blockIdx.x;
    const float* ob = obs + (size_t)b * (N_AG * DIM);

    // ---- load w_out (2048 floats = 512 float4) and b_out into smem ----
    {
        const float4* w4  = (const float4*)wout;
        float4*       ws4 = (float4*)ws;
        #pragma unroll
        for (int i = 0; i < 4; i++)
            ws4[i * 128 + tid] = w4[i * 128 + tid];
        if (tid < OUTD) bs[tid] = bout[tid];
    }

    // ---- stream obs tile: 2048 float4 coalesced LDG.128, STS.128 into pitched smem ----
    {
        const float4* o4 = (const float4*)ob;
        #pragma unroll
        for (int i = 0; i < 16; i++) {
            int v = i * 128 + tid;               // float4 index 0..2047
            float4 val = o4[v];
            int row = v >> 5;                    // 32 float4 per 128-float row
            int col = (v & 31) << 2;
            *(float4*)&s[row * PITCH + col] = val;
        }
    }
    __syncthreads();

    // ---- per-feature phases: thread tid owns column d = tid (conflict-free LDS) ----
    const float a1 = wH1[tid];
    const float a2 = wH2[tid];
    const float c2 = wC2[tid];

    float sum = 0.0f;
    #pragma unroll 8
    for (int n = 0; n < N_AG; n++)
        sum += tanh_fast(a1 * s[n * PITCH + tid]);

    const float inv = 1.0f / (float)(N_AG - 1);
    #pragma unroll 8
    for (int n = 0; n < N_AG; n++) {
        float x  = s[n * PITCH + tid];
        float h1 = tanh_fast(a1 * x);
        float c1 = (sum - h1) * inv;
        float h2 = tanh_fast(a2 * h1 + c2 * c1) + x;
        s[n * PITCH + tid] = h2;                 // own column: no race
    }
    __syncthreads();

    // ---- GEMV epilogue: thread -> (agent n, output half). 8 accumulators. ----
    const int n    = tid >> 1;
    const int half = tid & 1;
    const float* hrow = &s[n * PITCH];
    const float* wcol = &ws[half * 8];

    float acc0 = bs[half * 8 + 0], acc1 = bs[half * 8 + 1];
    float acc2 = bs[half * 8 + 2], acc3 = bs[half * 8 + 3];
    float acc4 = bs[half * 8 + 4], acc5 = bs[half * 8 + 5];
    float acc6 = bs[half * 8 + 6], acc7 = bs[half * 8 + 7];

    #pragma unroll 16
    for (int d = 0; d < DIM; d++) {
        float h   = hrow[d];
        float4 w0 = *(const float4*)&wcol[d * OUTD + 0];
        float4 w1 = *(const float4*)&wcol[d * OUTD + 4];
        acc0 = fmaf(h, w0.x, acc0);
        acc1 = fmaf(h, w0.y, acc1);
        acc2 = fmaf(h, w0.z, acc2);
        acc3 = fmaf(h, w0.w, acc3);
        acc4 = fmaf(h, w1.x, acc4);
        acc5 = fmaf(h, w1.y, acc5);
        acc6 = fmaf(h, w1.z, acc6);
        acc7 = fmaf(h, w1.w, acc7);
    }

    float* op = out + (size_t)b * (N_AG * OUTD) + n * OUTD + half * 8;
    float4 r0 = {acc0, acc1, acc2, acc3};
    float4 r1 = {acc4, acc5, acc6, acc7};
    *(float4*)(op + 0) = r0;                     // coalesced STG.128
    *(float4*)(op + 4) = r1;
}

extern "C" void kernel_launch(void* const* d_in, const int* in_sizes, int n_in,
                              void* d_out, int out_size) {
    const float* obs  = (const float*)d_in[0];
    const float* wH1  = (const float*)d_in[1];
    // d_in[2] = w_C1: multiplies C0 = 0 -> unused
    const float* wH2  = (const float*)d_in[3];
    const float* wC2  = (const float*)d_in[4];
    const float* wout = (const float*)d_in[5];
    const float* bout = (const float*)d_in[6];
    float* out = (float*)d_out;

    int B = in_sizes[0] / (N_AG * DIM);          // 8192
    commnet_kernel<<<B, 128>>>(obs, wH1, wH2, wC2, wout, bout, out);
}

// round 5
// speedup vs baseline: 1.1353x; 1.1353x over previous
#include <cuda_runtime.h>

// CommNet forward: B=8192, N=64, D=128, O=16
//   H1 = tanh(wH1*obs); C1 = (sum_n H1 - H1)/(N-1)
//   H2 = tanh(wH2*H1 + wC2*C1) + obs
//   out = H2 @ w_out + b_out
//
// One CTA per batch element, 128 threads.
// Phase math: thread d owns feature column d, obs column held in REGISTERS
// (no smem round-trip). Smem used only for H2 tile + w_out.
// GEMV: thread = (agent-pair p, out-quad q); rows p and p+32 -> conflict-free
// LDS.128 (pitch 132 floats => row stride 33 bank-quads, 33 % 8 == 1).

#define N_AG 64
#define DIM  128
#define OUTD 16
#define PITCH 132

__device__ __forceinline__ float tanh_fast(float x) {
    float y;
    asm("tanh.approx.f32 %0, %1;" : "=f"(y) : "f"(x));
    return y;
}

__global__ __launch_bounds__(128)
void commnet_kernel(const float* __restrict__ obs,
                    const float* __restrict__ wH1,
                    const float* __restrict__ wH2,
                    const float* __restrict__ wC2,
                    const float* __restrict__ wout,
                    const float* __restrict__ bout,
                    float* __restrict__ out)
{
    __shared__ float s[N_AG * PITCH];     // 33,792 B: H2 tile
    __shared__ float ws[DIM * OUTD];      //  8,192 B: w_out [d][o]
    __shared__ float bs[OUTD];

    const int tid = threadIdx.x;          // 0..127 = feature d
    const int b   = blockIdx.x;

    // ---- stage w_out / b_out (L2-resident, tiny) ----
    {
        const float4* w4  = (const float4*)wout;
        float4*       ws4 = (float4*)ws;
        #pragma unroll
        for (int i = 0; i < 4; i++)
            ws4[i * 128 + tid] = w4[i * 128 + tid];
        if (tid < OUTD) bs[tid] = bout[tid];
    }

    // ---- load obs column d=tid into registers: 64 coalesced LDG.32 ----
    const float* ob = obs + (size_t)b * (N_AG * DIM) + tid;
    float x[N_AG];
    #pragma unroll
    for (int n = 0; n < N_AG; n++)
        x[n] = ob[n * DIM];

    const float a1 = wH1[tid];
    const float a2 = wH2[tid];
    const float c2 = wC2[tid];

    // ---- pass 1: per-feature sum of tanh over agents (registers only) ----
    float sum = 0.0f;
    #pragma unroll
    for (int n = 0; n < N_AG; n++)
        sum += tanh_fast(a1 * x[n]);

    // ---- pass 2: H2 -> smem tile (own column: conflict-free STS.32) ----
    const float inv = 1.0f / (float)(N_AG - 1);
    #pragma unroll
    for (int n = 0; n < N_AG; n++) {
        float h1 = tanh_fast(a1 * x[n]);          // recompute: MUFU pipe idle
        float h2 = tanh_fast(a2 * h1 + c2 * (sum - h1) * inv) + x[n];
        s[n * PITCH + tid] = h2;
    }
    __syncthreads();

    // ---- GEMV: thread = (p = tid>>2, q = tid&3); agents p and p+32 ----
    const int p = tid >> 2;
    const int q = tid & 3;

    const float4* h0v = (const float4*)&s[p * PITCH];           // agent p
    const float4* h1v = (const float4*)&s[(p + 32) * PITCH];    // agent p+32

    float4 acc0 = *(const float4*)&bs[q * 4];
    float4 acc1 = acc0;

    #pragma unroll
    for (int c = 0; c < 32; c++) {                 // d = 4c .. 4c+3
        float4 ha = h0v[c];
        float4 hb = h1v[c];
        const float4* wr = (const float4*)&ws[c * 4 * OUTD] + q;  // w[4c][q*4]
        float4 w0 = wr[0];                          // d = 4c   (row = 4 float4)
        float4 w1 = wr[4];                          // d = 4c+1
        float4 w2 = wr[8];                          // d = 4c+2
        float4 w3 = wr[12];                         // d = 4c+3

        acc0.x = fmaf(ha.x, w0.x, acc0.x); acc0.y = fmaf(ha.x, w0.y, acc0.y);
        acc0.z = fmaf(ha.x, w0.z, acc0.z); acc0.w = fmaf(ha.x, w0.w, acc0.w);
        acc0.x = fmaf(ha.y, w1.x, acc0.x); acc0.y = fmaf(ha.y, w1.y, acc0.y);
        acc0.z = fmaf(ha.y, w1.z, acc0.z); acc0.w = fmaf(ha.y, w1.w, acc0.w);
        acc0.x = fmaf(ha.z, w2.x, acc0.x); acc0.y = fmaf(ha.z, w2.y, acc0.y);
        acc0.z = fmaf(ha.z, w2.z, acc0.z); acc0.w = fmaf(ha.z, w2.w, acc0.w);
        acc0.x = fmaf(ha.w, w3.x, acc0.x); acc0.y = fmaf(ha.w, w3.y, acc0.y);
        acc0.z = fmaf(ha.w, w3.z, acc0.z); acc0.w = fmaf(ha.w, w3.w, acc0.w);

        acc1.x = fmaf(hb.x, w0.x, acc1.x); acc1.y = fmaf(hb.x, w0.y, acc1.y);
        acc1.z = fmaf(hb.x, w0.z, acc1.z); acc1.w = fmaf(hb.x, w0.w, acc1.w);
        acc1.x = fmaf(hb.y, w1.x, acc1.x); acc1.y = fmaf(hb.y, w1.y, acc1.y);
        acc1.z = fmaf(hb.y, w1.z, acc1.z); acc1.w = fmaf(hb.y, w1.w, acc1.w);
        acc1.x = fmaf(hb.z, w2.x, acc1.x); acc1.y = fmaf(hb.z, w2.y, acc1.y);
        acc1.z = fmaf(hb.z, w2.z, acc1.z); acc1.w = fmaf(hb.z, w2.w, acc1.w);
        acc1.x = fmaf(hb.w, w3.x, acc1.x); acc1.y = fmaf(hb.w, w3.y, acc1.y);
        acc1.z = fmaf(hb.w, w3.z, acc1.z); acc1.w = fmaf(hb.w, w3.w, acc1.w);
    }

    // ---- store: out[b][n][q*4 .. q*4+4), agents p and p+32 ----
    float* ob_out = out + (size_t)b * (N_AG * OUTD) + q * 4;
    *(float4*)(ob_out + p * OUTD)        = acc0;
    *(float4*)(ob_out + (p + 32) * OUTD) = acc1;
}

extern "C" void kernel_launch(void* const* d_in, const int* in_sizes, int n_in,
                              void* d_out, int out_size) {
    const float* obs  = (const float*)d_in[0];
    const float* wH1  = (const float*)d_in[1];
    // d_in[2] = w_C1: multiplies C0 = 0 -> unused
    const float* wH2  = (const float*)d_in[3];
    const float* wC2  = (const float*)d_in[4];
    const float* wout = (const float*)d_in[5];
    const float* bout = (const float*)d_in[6];
    float* out = (float*)d_out;

    int B = in_sizes[0] / (N_AG * DIM);   // 8192
    commnet_kernel<<<B, 128>>>(obs, wH1, wH2, wC2, wout, bout, out);
}

// round 6
// speedup vs baseline: 1.2427x; 1.0946x over previous
#include <cuda_runtime.h>

// CommNet forward: B=8192, N=64, D=128, O=16
//   H1 = tanh(wH1*obs); C1 = (sum_n H1 - H1)/(N-1)
//   H2 = tanh(wH2*H1 + wC2*C1) + obs
//   out = H2 @ w_out + b_out
//
// One CTA per batch element, 128 threads.
// Phase math: thread d owns feature column d; obs column in registers.
// GEMV: warp = output-quad q (warp-uniform => w-loads are full-warp
// broadcast LDS.128 = 1 wavefront). Lane l owns agents {l, l+32}.
// Packed fp32x2 FMA (FFMA2) halves fma-pipe cycles.

#define N_AG 64
#define DIM  128
#define OUTD 16
#define PITCH 132   // row stride in floats: 33 bank-quads => lane-stride conflict-free

typedef unsigned long long u64;

__device__ __forceinline__ float tanh_fast(float x) {
    float y;
    asm("tanh.approx.f32 %0, %1;" : "=f"(y) : "f"(x));
    return y;
}
__device__ __forceinline__ u64 pack2(float lo, float hi) {
    u64 r;
    asm("mov.b64 %0, {%1, %2};" : "=l"(r) : "f"(lo), "f"(hi));
    return r;
}
__device__ __forceinline__ void ffma2(u64& d, u64 a, u64 b) {
    asm("fma.rn.f32x2 %0, %1, %2, %0;" : "+l"(d) : "l"(a), "l"(b));
}
__device__ __forceinline__ float2 unpack2(u64 v) {
    float2 f;
    asm("mov.b64 {%0, %1}, %2;" : "=f"(f.x), "=f"(f.y) : "l"(v));
    return f;
}

__global__ __launch_bounds__(128)
void commnet_kernel(const float* __restrict__ obs,
                    const float* __restrict__ wH1,
                    const float* __restrict__ wH2,
                    const float* __restrict__ wC2,
                    const float* __restrict__ wout,
                    const float* __restrict__ bout,
                    float* __restrict__ out)
{
    __shared__ __align__(16) float s[N_AG * PITCH];   // H2 tile
    __shared__ __align__(16) float ws[DIM * OUTD];    // w_out [d][o]
    __shared__ __align__(16) float bs[OUTD];

    const int tid = threadIdx.x;          // 0..127 = feature d (phase part)
    const int b   = blockIdx.x;

    // ---- stage w_out / b_out (L2-resident, tiny) ----
    {
        const float4* w4  = (const float4*)wout;
        float4*       ws4 = (float4*)ws;
        #pragma unroll
        for (int i = 0; i < 4; i++)
            ws4[i * 128 + tid] = w4[i * 128 + tid];
        if (tid < OUTD) bs[tid] = bout[tid];
    }

    // ---- obs column d=tid into registers: 64 coalesced LDG.32 ----
    const float* ob = obs + (size_t)b * (N_AG * DIM) + tid;
    float x[N_AG];
    #pragma unroll
    for (int n = 0; n < N_AG; n++)
        x[n] = ob[n * DIM];

    const float a1 = wH1[tid];
    const float a2 = wH2[tid];
    const float c2 = wC2[tid];

    // ---- pass 1: per-feature sum of tanh over agents (registers only) ----
    float sum = 0.0f;
    #pragma unroll
    for (int n = 0; n < N_AG; n++)
        sum += tanh_fast(a1 * x[n]);

    // ---- pass 2: H2 -> smem tile (own column: conflict-free STS.32) ----
    const float inv = 1.0f / (float)(N_AG - 1);
    #pragma unroll
    for (int n = 0; n < N_AG; n++) {
        float h1 = tanh_fast(a1 * x[n]);          // recompute: MUFU has headroom
        float h2 = tanh_fast(a2 * h1 + c2 * (sum - h1) * inv) + x[n];
        s[n * PITCH + tid] = h2;
    }
    __syncthreads();

    // ---- GEMV: warp q (out-quad, warp-uniform), lane l -> agents l, l+32 ----
    const int q = tid >> 5;                // 0..3, uniform within warp
    const int l = tid & 31;

    const float4* hr0 = (const float4*)&s[l * PITCH];          // agent l
    const float4* hr1 = (const float4*)&s[(l + 32) * PITCH];   // agent l+32

    u64 accA01, accA23, accB01, accB23;
    {
        const u64* bp = (const u64*)&bs[q * 4];                // 8B-aligned
        accA01 = bp[0]; accA23 = bp[1];
        accB01 = bp[0]; accB23 = bp[1];
    }

    #pragma unroll
    for (int c = 0; c < 32; c++) {
        float4 ha = hr0[c];                 // conflict-free: 32 distinct rows
        float4 hb = hr1[c];
        #pragma unroll
        for (int i = 0; i < 4; i++) {
            const int d = 4 * c + i;
            // all-lane broadcast LDS.128 (address depends only on d, q)
            ulonglong2 wv = *(const ulonglong2*)&ws[d * OUTD + q * 4];
            float hA = (i == 0) ? ha.x : (i == 1) ? ha.y : (i == 2) ? ha.z : ha.w;
            float hB = (i == 0) ? hb.x : (i == 1) ? hb.y : (i == 2) ? hb.z : hb.w;
            u64 hpA = pack2(hA, hA);
            u64 hpB = pack2(hB, hB);
            ffma2(accA01, hpA, wv.x);
            ffma2(accA23, hpA, wv.y);
            ffma2(accB01, hpB, wv.x);
            ffma2(accB23, hpB, wv.y);
        }
    }

    // ---- store: out[b][n][q*4 .. q*4+4) for agents l and l+32 ----
    float2 a0 = unpack2(accA01), a1v = unpack2(accA23);
    float2 b0 = unpack2(accB01), b1v = unpack2(accB23);
    float* op = out + (size_t)b * (N_AG * OUTD) + q * 4;
    *(float4*)(op + l * OUTD)        = make_float4(a0.x, a0.y, a1v.x, a1v.y);
    *(float4*)(op + (l + 32) * OUTD) = make_float4(b0.x, b0.y, b1v.x, b1v.y);
}

extern "C" void kernel_launch(void* const* d_in, const int* in_sizes, int n_in,
                              void* d_out, int out_size) {
    const float* obs  = (const float*)d_in[0];
    const float* wH1  = (const float*)d_in[1];
    // d_in[2] = w_C1: multiplies C0 = 0 -> unused
    const float* wH2  = (const float*)d_in[3];
    const float* wC2  = (const float*)d_in[4];
    const float* wout = (const float*)d_in[5];
    const float* bout = (const float*)d_in[6];
    float* out = (float*)d_out;

    int B = in_sizes[0] / (N_AG * DIM);   // 8192
    commnet_kernel<<<B, 128>>>(obs, wH1, wH2, wC2, wout, bout, out);
}